// round 5
// baseline (speedup 1.0000x reference)
#include <cuda_runtime.h>
#include <math.h>

#define N_NODES 100000
#define N_EDGES 800000
#define NG 64
#define HID 64
#define EMB 128

// ---------------- device scratch (static allocation only) ----------------
__device__ float g_bufA[N_NODES * HID];   // hop1
__device__ float g_bufB[N_NODES * HID];   // hop2
__device__ float g_bufC[N_NODES * HID];   // hop3
__device__ float g_bufD[N_NODES * HID];   // layer output
__device__ float g_dn  [N_NODES];
__device__ int   g_deg [N_NODES];
__device__ int   g_fill[N_NODES];
__device__ int   g_rowptr[N_NODES + 1];
__device__ int   g_csr[N_EDGES];
__device__ float g_gsum[NG * HID];
__device__ int   g_gcnt[NG];

__device__ __forceinline__ float* buf_sel(int s) {
    return (s == 0) ? g_bufA : (s == 1) ? g_bufB : (s == 2) ? g_bufC : g_bufD;
}

// ---------------- init / CSR build ----------------
__global__ void k_init() {
    int i = blockIdx.x * blockDim.x + threadIdx.x;
    if (i < N_NODES) { g_deg[i] = 0; g_fill[i] = 0; }
    if (i < NG * HID) g_gsum[i] = 0.f;
    if (i < NG)       g_gcnt[i] = 0;
}

__global__ void k_deg(const int* __restrict__ dst) {
    int e = blockIdx.x * blockDim.x + threadIdx.x;
    if (e < N_EDGES) atomicAdd(&g_deg[dst[e]], 1);
}

// single-block scan (1024 threads) -> rowptr, dn
__global__ void k_scan() {
    __shared__ int sa[1024], sb[1024];
    int t = threadIdx.x;
    const int CH = (N_NODES + 1023) / 1024;   // 98
    int base = t * CH;
    int local = 0;
    for (int i = 0; i < CH; i++) {
        int idx = base + i;
        if (idx < N_NODES) local += g_deg[idx];
    }
    sa[t] = local;
    __syncthreads();
    int* cur = sa; int* nxt = sb;
    for (int off = 1; off < 1024; off <<= 1) {
        int v = cur[t] + ((t >= off) ? cur[t - off] : 0);
        nxt[t] = v;
        __syncthreads();
        int* tmp = cur; cur = nxt; nxt = tmp;
    }
    int excl = cur[t] - local;
    int run = excl;
    for (int i = 0; i < CH; i++) {
        int idx = base + i;
        if (idx < N_NODES) {
            g_rowptr[idx] = run;
            int d = g_deg[idx];
            run += d;
            g_dn[idx] = rsqrtf((float)(d > 1 ? d : 1));
        }
    }
    if (t == 1023) g_rowptr[N_NODES] = run;   // == N_EDGES
}

__global__ void k_fill(const int* __restrict__ src, const int* __restrict__ dst) {
    int e = blockIdx.x * blockDim.x + threadIdx.x;
    if (e < N_EDGES) {
        int d = dst[e];
        int pos = g_rowptr[d] + atomicAdd(&g_fill[d], 1);
        g_csr[pos] = src[e];
    }
}

// ---------------- SpMM: xout[r] = dn[r] * sum_{s in N_in(r)} dn[s]*xin[s] ----------------
// warp per row; edge loop unrolled x4 for MLP
__global__ void __launch_bounds__(256) k_spmm(const float* __restrict__ xin_ext,
                                              int in_sel, int out_sel) {
    const float* xin = (in_sel < 0) ? xin_ext : buf_sel(in_sel);
    float* xout = buf_sel(out_sel);
    int w = (blockIdx.x * blockDim.x + threadIdx.x) >> 5;
    if (w >= N_NODES) return;
    int lane = threadIdx.x & 31;
    int e0 = g_rowptr[w], e1 = g_rowptr[w + 1];
    float a0 = 0.f, a1 = 0.f, b0 = 0.f, b1 = 0.f;
    float c0 = 0.f, c1 = 0.f, d0 = 0.f, d1 = 0.f;
    int e = e0;
    for (; e + 4 <= e1; e += 4) {
        int s0 = g_csr[e], s1 = g_csr[e + 1], s2 = g_csr[e + 2], s3 = g_csr[e + 3];
        float w0 = g_dn[s0], w1 = g_dn[s1], w2 = g_dn[s2], w3 = g_dn[s3];
        float2 v0 = *(const float2*)(xin + (size_t)s0 * HID + lane * 2);
        float2 v1 = *(const float2*)(xin + (size_t)s1 * HID + lane * 2);
        float2 v2 = *(const float2*)(xin + (size_t)s2 * HID + lane * 2);
        float2 v3 = *(const float2*)(xin + (size_t)s3 * HID + lane * 2);
        a0 = fmaf(v0.x, w0, a0); a1 = fmaf(v0.y, w0, a1);
        b0 = fmaf(v1.x, w1, b0); b1 = fmaf(v1.y, w1, b1);
        c0 = fmaf(v2.x, w2, c0); c1 = fmaf(v2.y, w2, c1);
        d0 = fmaf(v3.x, w3, d0); d1 = fmaf(v3.y, w3, d1);
    }
    for (; e < e1; ++e) {
        int s = g_csr[e];
        float wt = g_dn[s];
        float2 v = *(const float2*)(xin + (size_t)s * HID + lane * 2);
        a0 = fmaf(v.x, wt, a0);
        a1 = fmaf(v.y, wt, a1);
    }
    float wd = g_dn[w];
    float2 o;
    o.x = ((a0 + b0) + (c0 + d0)) * wd;
    o.y = ((a1 + b1) + (c1 + d1)) * wd;
    *(float2*)(xout + (size_t)w * HID + lane * 2) = o;
}

// ---------------- fused layer GEMM:
//   D = relu( in@W0c + hop1@W1c + hop2@W2c + hop3@W3c + b )
// W is [(4*64) x 64] row-major; sources: {in, bufA, bufB, bufC}.
// block: 128 threads, tile 64 rows x 64 cols, micro 8x4, acc in registers
__global__ void __launch_bounds__(128) k_gemm4(const float* __restrict__ in_ext, int in_sel,
                                               const float* __restrict__ W,
                                               const float* __restrict__ bias,
                                               int out_sel) {
    __shared__ float xs[64 * 72];   // stride 72 floats (pad) - conflict free
    __shared__ float ws[64 * 64];
    int t = threadIdx.x;            // 0..127
    int rowBase = blockIdx.x * 64;

    int r0 = (t >> 4) * 8;     // 0..56
    int c0 = (t & 15) * 4;     // 0..60
    float acc[8][4];
#pragma unroll
    for (int i = 0; i < 8; i++)
#pragma unroll
        for (int j = 0; j < 4; j++) acc[i][j] = 0.f;

    const float* in0 = (in_sel < 0) ? in_ext : buf_sel(in_sel);

    for (int s = 0; s < 4; ++s) {
        const float* A = (s == 0) ? in0 : buf_sel(s - 1);   // A,B,C for s=1,2,3
        const float* Wc = W + s * 64 * 64;

        // load W chunk (1024 float4; 128 threads x 8)
        const float4* W4 = (const float4*)Wc;
        float4* ws4 = (float4*)ws;
#pragma unroll
        for (int i = 0; i < 8; i++) ws4[t + 128 * i] = W4[t + 128 * i];

        // load A tile: 64 rows x 16 float4
#pragma unroll
        for (int i = 0; i < 8; i++) {
            int l = t + 128 * i;
            int r = l >> 4, k4 = l & 15;
            int grow = rowBase + r;
            float4 v = make_float4(0.f, 0.f, 0.f, 0.f);
            if (grow < N_NODES) v = ((const float4*)A)[(size_t)grow * 16 + k4];
            *(float4*)&xs[r * 72 + k4 * 4] = v;
        }
        __syncthreads();

#pragma unroll 4
        for (int k = 0; k < 64; k += 4) {
            float4 wv0 = *(float4*)&ws[(k + 0) * 64 + c0];
            float4 wv1 = *(float4*)&ws[(k + 1) * 64 + c0];
            float4 wv2 = *(float4*)&ws[(k + 2) * 64 + c0];
            float4 wv3 = *(float4*)&ws[(k + 3) * 64 + c0];
#pragma unroll
            for (int i = 0; i < 8; i++) {
                float4 xv = *(float4*)&xs[(r0 + i) * 72 + k];
                acc[i][0] = fmaf(xv.x, wv0.x, acc[i][0]);
                acc[i][0] = fmaf(xv.y, wv1.x, acc[i][0]);
                acc[i][0] = fmaf(xv.z, wv2.x, acc[i][0]);
                acc[i][0] = fmaf(xv.w, wv3.x, acc[i][0]);
                acc[i][1] = fmaf(xv.x, wv0.y, acc[i][1]);
                acc[i][1] = fmaf(xv.y, wv1.y, acc[i][1]);
                acc[i][1] = fmaf(xv.z, wv2.y, acc[i][1]);
                acc[i][1] = fmaf(xv.w, wv3.y, acc[i][1]);
                acc[i][2] = fmaf(xv.x, wv0.z, acc[i][2]);
                acc[i][2] = fmaf(xv.y, wv1.z, acc[i][2]);
                acc[i][2] = fmaf(xv.z, wv2.z, acc[i][2]);
                acc[i][2] = fmaf(xv.w, wv3.z, acc[i][2]);
                acc[i][3] = fmaf(xv.x, wv0.w, acc[i][3]);
                acc[i][3] = fmaf(xv.y, wv1.w, acc[i][3]);
                acc[i][3] = fmaf(xv.z, wv2.w, acc[i][3]);
                acc[i][3] = fmaf(xv.w, wv3.w, acc[i][3]);
            }
        }
        __syncthreads();   // protect xs/ws before next source overwrites
    }

    float* outbuf = buf_sel(out_sel);
    float4 bv = *(const float4*)&bias[c0];
#pragma unroll
    for (int i = 0; i < 8; i++) {
        int grow = rowBase + r0 + i;
        if (grow < N_NODES) {
            float4 v;
            v.x = fmaxf(acc[i][0] + bv.x, 0.f);
            v.y = fmaxf(acc[i][1] + bv.y, 0.f);
            v.z = fmaxf(acc[i][2] + bv.z, 0.f);
            v.w = fmaxf(acc[i][3] + bv.w, 0.f);
            *(float4*)&outbuf[(size_t)grow * 64 + c0] = v;
        }
    }
}

// ---------------- readout: segmented mean over sorted graph_ids ----------------
__global__ void k_readout(int in_sel, const int* __restrict__ gid) {
    const float* h = buf_sel(in_sel);
    const int ROWS = 64;
    int w = (blockIdx.x * blockDim.x + threadIdx.x) >> 5;
    int nwarps = (N_NODES + ROWS - 1) / ROWS;
    if (w >= nwarps) return;
    int lane = threadIdx.x & 31;
    int r = w * ROWS;
    int rend = r + ROWS; if (rend > N_NODES) rend = N_NODES;
    int g = gid[r];
    float s0 = 0.f, s1 = 0.f; int cnt = 0;
    for (; r < rend; ++r) {
        int g2 = gid[r];
        if (g2 != g) {
            atomicAdd(&g_gsum[g * HID + lane], s0);
            atomicAdd(&g_gsum[g * HID + 32 + lane], s1);
            if (lane == 0) atomicAdd(&g_gcnt[g], cnt);
            s0 = 0.f; s1 = 0.f; cnt = 0; g = g2;
        }
        s0 += h[(size_t)r * HID + lane];
        s1 += h[(size_t)r * HID + 32 + lane];
        cnt++;
    }
    atomicAdd(&g_gsum[g * HID + lane], s0);
    atomicAdd(&g_gsum[g * HID + 32 + lane], s1);
    if (lane == 0) atomicAdd(&g_gcnt[g], cnt);
}

// ---------------- final: hg = mean; out = normalize(hg @ embW + embb) ----------------
__global__ void k_final(const float* __restrict__ embW, const float* __restrict__ embb,
                        float* __restrict__ out) {
    __shared__ float hg[HID];
    __shared__ float red[EMB];
    int g = blockIdx.x, t = threadIdx.x;  // t: 0..127
    if (t < HID) {
        float c = (float)g_gcnt[g];
        hg[t] = g_gsum[g * HID + t] / fmaxf(c, 1.f);
    }
    __syncthreads();
    float a = embb[t];
#pragma unroll
    for (int i = 0; i < HID; i++) a = fmaf(hg[i], embW[i * EMB + t], a);
    red[t] = a * a;
    __syncthreads();
    for (int s = 64; s > 0; s >>= 1) {
        if (t < s) red[t] += red[t + s];
        __syncthreads();
    }
    float nrm = fmaxf(sqrtf(red[0]), 1e-12f);
    out[g * EMB + t] = a / nrm;
}

// ---------------- launch (pure kernel launches; no runtime API calls) --------
extern "C" void kernel_launch(void* const* d_in, const int* in_sizes, int n_in,
                              void* d_out, int out_size) {
    const float* h     = (const float*)d_in[0];
    const int*   src   = (const int*)  d_in[1];
    const int*   dst   = (const int*)  d_in[2];
    const int*   gid   = (const int*)  d_in[3];
    const float* W0    = (const float*)d_in[4];
    const float* b0    = (const float*)d_in[5];
    const float* W1    = (const float*)d_in[6];
    const float* b1    = (const float*)d_in[7];
    const float* W2    = (const float*)d_in[8];
    const float* b2    = (const float*)d_in[9];
    const float* embW  = (const float*)d_in[10];
    const float* embb  = (const float*)d_in[11];
    float* out = (float*)d_out;

    // build CSR + deg norm
    k_init<<<(N_NODES + 255) / 256, 256>>>();
    k_deg<<<(N_EDGES + 255) / 256, 256>>>(dst);
    k_scan<<<1, 1024>>>();
    k_fill<<<(N_EDGES + 255) / 256, 256>>>(src, dst);

    const int SPMM_BLOCKS = (N_NODES * 32 + 255) / 256;
    const int GEMM_BLOCKS = (N_NODES + 63) / 64;

    const float* Ws[3] = {W0, W1, W2};
    const float* bs[3] = {b0, b1, b2};

    // buffer selectors: 0 = bufA (hop1), 1 = bufB (hop2), 2 = bufC (hop3), 3 = bufD (layer out)
    int in_sel = -1;                 // layer input: external h for L0, else bufD
    const float* in_ext = h;
    for (int L = 0; L < 3; ++L) {
        k_spmm<<<SPMM_BLOCKS, 256>>>(in_ext, in_sel, 0);     // in -> A
        k_spmm<<<SPMM_BLOCKS, 256>>>(nullptr, 0, 1);         // A  -> B
        k_spmm<<<SPMM_BLOCKS, 256>>>(nullptr, 1, 2);         // B  -> C
        k_gemm4<<<GEMM_BLOCKS, 128>>>(in_ext, in_sel, Ws[L], bs[L], 3);  // -> D
        in_sel = 3; in_ext = nullptr;
    }

    // readout on bufD (sel 3)
    const int RO_WARPS = (N_NODES + 63) / 64;
    k_readout<<<(RO_WARPS * 32 + 255) / 256, 256>>>(3, gid);
    k_final<<<NG, EMB>>>(embW, embb, out);
}